// round 6
// baseline (speedup 1.0000x reference)
#include <cuda_runtime.h>
#include <cuda_bf16.h>
#include <cooperative_groups.h>
#include <math.h>

namespace cg = cooperative_groups;

#define Bsz 32
#define Ssz 1024
#define Hsz 256
#define G4  1024
#define NROWS_S 216   // W_hh rows held in SMEM per CTA (of 256 owned)

// 134 MB scratch: WX[b,s,j] = enc[b,s,:]·W_ih[j,:] + b_ih[j] + b_hh[j]
__device__ float g_WX[(size_t)Bsz * Ssz * G4];

// ---------------------------------------------------------------------------
// Kernel 1: WX = enc @ W_ih^T + (b_ih + b_hh)   (fp32 tiled GEMM)
// A: [32768, 256] row-major (enc flattened), Wb: [1024, 256] row-major
// ---------------------------------------------------------------------------
__global__ __launch_bounds__(256) void wx_gemm(
    const float* __restrict__ A,
    const float* __restrict__ Wb,
    const float* __restrict__ b_ih,
    const float* __restrict__ b_hh)
{
  __shared__ float As[16][64];   // transposed tiles: [k][m]
  __shared__ float Bs[16][64];   // [k][n]
  const int tid  = threadIdx.x;
  const int row0 = blockIdx.y * 64;
  const int col0 = blockIdx.x * 64;
  const int lr = tid >> 2;
  const int lc = (tid & 3) * 4;
  const int ty = tid >> 4, tx = tid & 15;
  float acc[4][4] = {};

  for (int k0 = 0; k0 < 256; k0 += 16) {
    float4 av = *(const float4*)(A  + (size_t)(row0 + lr) * 256 + k0 + lc);
    float4 bv = *(const float4*)(Wb + (size_t)(col0 + lr) * 256 + k0 + lc);
    As[lc + 0][lr] = av.x; As[lc + 1][lr] = av.y;
    As[lc + 2][lr] = av.z; As[lc + 3][lr] = av.w;
    Bs[lc + 0][lr] = bv.x; Bs[lc + 1][lr] = bv.y;
    Bs[lc + 2][lr] = bv.z; Bs[lc + 3][lr] = bv.w;
    __syncthreads();
#pragma unroll
    for (int kk = 0; kk < 16; kk++) {
      float4 a4 = *(const float4*)&As[kk][ty * 4];
      float4 b4 = *(const float4*)&Bs[kk][tx * 4];
      float a[4]  = {a4.x, a4.y, a4.z, a4.w};
      float bb[4] = {b4.x, b4.y, b4.z, b4.w};
#pragma unroll
      for (int i = 0; i < 4; i++)
#pragma unroll
        for (int j = 0; j < 4; j++) acc[i][j] += a[i] * bb[j];
    }
    __syncthreads();
  }
#pragma unroll
  for (int i = 0; i < 4; i++) {
    int rr = row0 + ty * 4 + i;
#pragma unroll
    for (int j = 0; j < 4; j++) {
      int cc = col0 + tx * 4 + j;
      g_WX[(size_t)rr * G4 + cc] = acc[i][j] + b_ih[cc] + b_hh[cc];
    }
  }
}

// ---------------------------------------------------------------------------
// Kernel 2: sequential decoder. One 4-CTA cluster per batch.
// CTA r of the cluster owns: gate rows {g*256 + r*64 + k : g<4, k<64},
// hidden lanes [r*64, r*64+64), score positions [r*256, r*256+256).
// ---------------------------------------------------------------------------
__global__ void __cluster_dims__(4, 1, 1) __launch_bounds__(512, 1)
decoder_main(const float* __restrict__ enc,
             const float* __restrict__ W_hh,
             const float* __restrict__ b_ih,
             const float* __restrict__ b_hh,
             float* __restrict__ out)
{
  extern __shared__ float sm[];
  float* Whh_s    = sm;                         // NROWS_S * 256
  float* h_buf    = Whh_s + NROWS_S * 256;      // 2 * 256 (double buffer)
  float* c_s      = h_buf + 512;                // 64
  float* gates_s  = c_s + 64;                   // 256
  float* scores_s = gates_s + 256;              // 256 (scores, then exp values)
  float* red_m    = scores_s + 256;             // 16
  float* red_s    = red_m + 16;                 // 16
  int*   red_i    = (int*)(red_s + 16);         // 16
  float* tup_m    = (float*)(red_i + 16);       // 4 (per-CTA max)
  float* tup_s    = tup_m + 4;                  // 4 (per-CTA sumexp @ local max)
  int*   tup_i    = (int*)(tup_s + 4);          // 4 (per-CTA argmax, global s)
  float* sh_ml    = (float*)(tup_i + 4);        // 1
  int*   sh_ai    = (int*)(sh_ml + 1);          // 1

  cg::cluster_group cluster = cg::this_cluster();
  const int tid  = threadIdx.x;
  const int w    = tid >> 5, lane = tid & 31;
  const int r    = blockIdx.x & 3;   // rank in cluster
  const int b    = blockIdx.x >> 2;  // batch
  const float* encb = enc + (size_t)b * Ssz * Hsz;

  // ---- init: load this CTA's W_hh rows into SMEM; zero state ----
  for (int i4 = tid; i4 < NROWS_S * 64; i4 += 512) {
    int l = i4 >> 6, c4 = i4 & 63;
    int j = (l >> 6) * 256 + r * 64 + (l & 63);   // valid for all l in [0,256)
    ((float4*)Whh_s)[i4] = *((const float4*)(W_hh + (size_t)j * 256) + c4);
  }
  if (tid < 512) h_buf[tid] = 0.f;
  if (tid < 64)  c_s[tid]   = 0.f;
  __syncthreads();
  cluster.sync();

  int idx = 0;  // pointer index from previous step (unused at t==0)

  for (int t = 0; t < Ssz; t++) {
    const int p = t & 1;

    // (A) prefetch x-gate contribution (WX row of previous argmax; bias at t=0)
    float wx0 = 0.f, wx1 = 0.f, wx2 = 0.f, wx3 = 0.f;
    if (tid < 64) {
      if (t == 0) {
        int jb = r * 64 + tid;
        wx0 = b_ih[jb]       + b_hh[jb];
        wx1 = b_ih[256 + jb] + b_hh[256 + jb];
        wx2 = b_ih[512 + jb] + b_hh[512 + jb];
        wx3 = b_ih[768 + jb] + b_hh[768 + jb];
      } else {
        const float* wxr = g_WX + ((size_t)b * Ssz + idx) * G4 + r * 64 + tid;
        wx0 = wxr[0]; wx1 = wxr[256]; wx2 = wxr[512]; wx3 = wxr[768];
      }
    }

    // (B) recurrent gate GEMV: gates[l] = W_hh[j(l),:] · h_prev
    {
      const float4* h4 = (const float4*)(h_buf + p * 256);
      float4 h0 = h4[lane], h1 = h4[32 + lane];
#pragma unroll
      for (int ii = 0; ii < 16; ii++) {
        int l = w * 16 + ii;
        float4 w0, w1;
        if (l < NROWS_S) {
          const float4* wr = (const float4*)Whh_s + (size_t)l * 64;
          w0 = wr[lane]; w1 = wr[32 + lane];
        } else {
          int j = 768 + r * 64 + (l - 192);
          const float4* wr = (const float4*)(W_hh + (size_t)j * 256);
          w0 = wr[lane]; w1 = wr[32 + lane];
        }
        float acc = w0.x*h0.x + w0.y*h0.y + w0.z*h0.z + w0.w*h0.w
                  + w1.x*h1.x + w1.y*h1.y + w1.z*h1.z + w1.w*h1.w;
#pragma unroll
        for (int off = 16; off; off >>= 1)
          acc += __shfl_down_sync(0xffffffffu, acc, off);
        if (lane == 0) gates_s[l] = acc;
      }
    }
    __syncthreads();

    // (C) LSTM cell for owned lanes; broadcast new h chunk to whole cluster
    if (tid < 64) {
      float gi = gates_s[tid]       + wx0;
      float gf = gates_s[64  + tid] + wx1;
      float gg = gates_s[128 + tid] + wx2;
      float go = gates_s[192 + tid] + wx3;
      float iv = 1.f / (1.f + expf(-gi));
      float fv = 1.f / (1.f + expf(-gf));
      float gv = tanhf(gg);
      float ov = 1.f / (1.f + expf(-go));
      float c  = fv * c_s[tid] + iv * gv;
      c_s[tid] = c;
      float hk = ov * tanhf(c);
      float* hl = &h_buf[(p ^ 1) * 256 + r * 64 + tid];
#pragma unroll
      for (int dst = 0; dst < 4; dst++)
        *cluster.map_shared_rank(hl, dst) = hk;
    }
    cluster.sync();  // new h visible cluster-wide

    // (E) attention scores for owned 256 encoder positions
    {
      const float4* h4 = (const float4*)(h_buf + (p ^ 1) * 256);
      float4 h0 = h4[lane], h1 = h4[32 + lane];
#pragma unroll
      for (int ii = 0; ii < 16; ii++) {
        int sl = w * 16 + ii;
        const float4* er = (const float4*)(encb + (size_t)(r * 256 + sl) * Hsz);
        float4 e0 = er[lane], e1 = er[32 + lane];
        float acc = e0.x*h0.x + e0.y*h0.y + e0.z*h0.z + e0.w*h0.w
                  + e1.x*h1.x + e1.y*h1.y + e1.z*h1.z + e1.w*h1.w;
#pragma unroll
        for (int off = 16; off; off >>= 1)
          acc += __shfl_down_sync(0xffffffffu, acc, off);
        if (lane == 0) scores_s[sl] = acc;
      }
    }
    __syncthreads();

    // (F) per-CTA (max, argmax, sumexp) — argmax ties -> lowest index
    float sc = (tid < 256) ? scores_s[tid] : -INFINITY;
    int   si = (tid < 256) ? (r * 256 + tid) : 0x7fffffff;
    {
      float m = sc; int mi = si;
#pragma unroll
      for (int off = 16; off; off >>= 1) {
        float om = __shfl_down_sync(0xffffffffu, m, off);
        int   oi = __shfl_down_sync(0xffffffffu, mi, off);
        if (om > m || (om == m && oi < mi)) { m = om; mi = oi; }
      }
      if (lane == 0) { red_m[w] = m; red_i[w] = mi; }
    }
    __syncthreads();
    if (w == 0) {
      float m = (lane < 16) ? red_m[lane] : -INFINITY;
      int  mi = (lane < 16) ? red_i[lane] : 0x7fffffff;
#pragma unroll
      for (int off = 8; off; off >>= 1) {
        float om = __shfl_down_sync(0xffffffffu, m, off);
        int   oi = __shfl_down_sync(0xffffffffu, mi, off);
        if (om > m || (om == m && oi < mi)) { m = om; mi = oi; }
      }
      if (lane == 0) { sh_ml[0] = m; sh_ai[0] = mi; }
    }
    __syncthreads();
    const float mloc = sh_ml[0];
    float e = (tid < 256) ? __expf(sc - mloc) : 0.f;
    if (tid < 256) scores_s[tid] = e;
    {
      float ssum = e;
#pragma unroll
      for (int off = 16; off; off >>= 1)
        ssum += __shfl_down_sync(0xffffffffu, ssum, off);
      if (lane == 0) red_s[w] = ssum;
    }
    __syncthreads();
    if (tid == 0) {
      float S = 0.f;
#pragma unroll
      for (int q = 0; q < 16; q++) S += red_s[q];
      int ai = sh_ai[0];
#pragma unroll
      for (int dst = 0; dst < 4; dst++) {
        *cluster.map_shared_rank(&tup_m[r], dst) = mloc;
        *cluster.map_shared_rank(&tup_s[r], dst) = S;
        *cluster.map_shared_rank(&tup_i[r], dst) = ai;
      }
    }
    cluster.sync();  // tuples visible cluster-wide

    // (H) combine tuples (redundantly per thread): global max/sum/argmax;
    //     write softmax probs; set next pointer index.
    float gm = tup_m[0]; int gq = 0;
#pragma unroll
    for (int q = 1; q < 4; q++) {
      float mq = tup_m[q];
      if (mq > gm) { gm = mq; gq = q; }   // strict > keeps lowest q on ties
    }
    float gsum = 0.f;
#pragma unroll
    for (int q = 0; q < 4; q++) gsum += tup_s[q] * __expf(tup_m[q] - gm);
    idx = tup_i[gq];
    if (tid < 256) {
      float scale = __expf(mloc - gm) / gsum;
      out[((size_t)b * Ssz + t) * Ssz + r * 256 + tid] = scores_s[tid] * scale;
    }
  }
}

// ---------------------------------------------------------------------------
extern "C" void kernel_launch(void* const* d_in, const int* in_sizes, int n_in,
                              void* d_out, int out_size)
{
  const float* enc  = (const float*)d_in[0];  // [32,1024,256]
  const float* W_ih = (const float*)d_in[1];  // [1024,256]
  const float* W_hh = (const float*)d_in[2];  // [1024,256]
  const float* b_ih = (const float*)d_in[3];  // [1024]
  const float* b_hh = (const float*)d_in[4];  // [1024]
  float* out = (float*)d_out;                 // [32,1024,1024]

  // Phase 1: WX = enc @ W_ih^T + biases   (M=32768, N=1024, K=256)
  dim3 g1(G4 / 64, (Bsz * Ssz) / 64);
  wx_gemm<<<g1, 256>>>(enc, W_ih, b_ih, b_hh);

  // Phase 2: sequential decoder, 32 clusters x 4 CTAs, 512 threads
  const int smem_bytes = (NROWS_S * 256 + 512 + 64 + 256 + 256
                          + 16 + 16 + 16 + 4 + 4 + 4 + 2) * 4;
  cudaFuncSetAttribute(decoder_main,
                       cudaFuncAttributeMaxDynamicSharedMemorySize, smem_bytes);
  decoder_main<<<Bsz * 4, 512, smem_bytes>>>(enc, W_hh, b_ih, b_hh, out);
}